// round 3
// baseline (speedup 1.0000x reference)
#include <cuda_runtime.h>

#define NQ      4
#define DIM     16      // 2^NQ
#define NHEADS  8
#define NLAYERS 2
#define EMBED   32
#define NBASIS  81      // 3^4 basis terms {1,cos,sin}^4

typedef unsigned long long u64;

// Staged coefficients (device global, filled by precompute, copied to smem
// by each main block).
struct CoefData {
    float4 C[NHEADS * NBASIS];   // C[h*81+k]: 4 Z-expval coeffs for basis k
    float4 Wt4[32][8];           // Wt4[j][e4].k = W_out[e4*4+k][j]
    float4 b4[8];
};
__device__ CoefData g_stage;

#define COEF_F4 (sizeof(CoefData) / 16)   // 912 float4s

// ---- packed f32x2 helpers (PTX-only; ptxas never auto-fuses FFMA2) ----
__device__ __forceinline__ u64 fma2(u64 a, u64 b, u64 c) {
    u64 d;
    asm("fma.rn.f32x2 %0, %1, %2, %3;" : "=l"(d) : "l"(a), "l"(b), "l"(c));
    return d;
}
__device__ __forceinline__ u64 pack2(float x, float y) {
    u64 d;
    asm("mov.b64 %0, {%1, %2};" : "=l"(d) : "f"(x), "f"(y));
    return d;
}
__device__ __forceinline__ float2 unpack2(u64 v) {
    float2 r;
    asm("mov.b64 {%0, %1}, %2;" : "=f"(r.x), "=f"(r.y) : "l"(v));
    return r;
}

// ---------------------------------------------------------------------------
// Precompute (unchanged math): build U per head, A_i = Re(U^H Z_i U),
// project onto {1,cos,sin}^4 basis. Block 0 packs Wt4/b4.
// ---------------------------------------------------------------------------
__global__ void qmha_precompute(const float* __restrict__ params,
                                const float* __restrict__ W,
                                const float* __restrict__ b) {
    __shared__ float Ur[DIM][DIM];
    __shared__ float Ui[DIM][DIM];
    __shared__ float A[NQ][DIM * DIM];

    const int h   = blockIdx.x;
    const int tid = threadIdx.x;

    if (tid < DIM) {
        float re[DIM], im[DIM];
        #pragma unroll
        for (int s = 0; s < DIM; s++) { re[s] = 0.f; im[s] = 0.f; }
        re[tid] = 1.f;

        const float* ph = params + h * NLAYERS * NQ * 3;

        #pragma unroll
        for (int l = 0; l < NLAYERS; l++) {
            #pragma unroll
            for (int w = 0; w < NQ; w++) {
                const int mask = 1 << (3 - w);
                float tx = ph[(l * NQ + w) * 3 + 0];
                float ty = ph[(l * NQ + w) * 3 + 1];
                float tz = ph[(l * NQ + w) * 3 + 2];
                float cx = cosf(0.5f * tx), sx = sinf(0.5f * tx);
                float cy = cosf(0.5f * ty), sy = sinf(0.5f * ty);
                float cz = cosf(0.5f * tz), sz = sinf(0.5f * tz);
                #pragma unroll
                for (int s0 = 0; s0 < DIM; s0++) {
                    if (s0 & mask) continue;
                    const int s1 = s0 | mask;
                    float r0 = re[s0], i0 = im[s0], r1 = re[s1], i1 = im[s1];
                    float nr0 = cx * r0 + sx * i1;
                    float ni0 = cx * i0 - sx * r1;
                    float nr1 = sx * i0 + cx * r1;
                    float ni1 = -sx * r0 + cx * i1;
                    r0 = nr0; i0 = ni0; r1 = nr1; i1 = ni1;
                    nr0 = cy * r0 - sy * r1;
                    ni0 = cy * i0 - sy * i1;
                    nr1 = sy * r0 + cy * r1;
                    ni1 = sy * i0 + cy * i1;
                    r0 = nr0; i0 = ni0; r1 = nr1; i1 = ni1;
                    re[s0] = cz * r0 + sz * i0;
                    im[s0] = cz * i0 - sz * r0;
                    re[s1] = cz * r1 - sz * i1;
                    im[s1] = cz * i1 + sz * r1;
                }
            }
            #pragma unroll
            for (int e = 0; e < NQ; e++) {
                const int c = e, t = (e + 1) & 3;
                const int cm = 1 << (3 - c), tm = 1 << (3 - t);
                #pragma unroll
                for (int s = 0; s < DIM; s++) {
                    if ((s & cm) && !(s & tm)) {
                        const int s2 = s | tm;
                        float tr = re[s]; re[s] = re[s2]; re[s2] = tr;
                        float ti = im[s]; im[s] = im[s2]; im[s2] = ti;
                    }
                }
            }
        }
        #pragma unroll
        for (int s = 0; s < DIM; s++) { Ur[tid][s] = re[s]; Ui[tid][s] = im[s]; }
    }
    __syncthreads();

    {
        const int p = tid >> 4, q = tid & 15;
        float a0 = 0.f, a1 = 0.f, a2 = 0.f, a3 = 0.f;
        #pragma unroll
        for (int s = 0; s < DIM; s++) {
            float rr = Ur[p][s] * Ur[q][s] + Ui[p][s] * Ui[q][s];
            a0 += (s & 8) ? -rr : rr;
            a1 += (s & 4) ? -rr : rr;
            a2 += (s & 2) ? -rr : rr;
            a3 += (s & 1) ? -rr : rr;
        }
        A[0][tid] = a0; A[1][tid] = a1; A[2][tid] = a2; A[3][tid] = a3;
    }
    __syncthreads();

    if (tid < NBASIS) {
        int kw[4] = {tid / 27, (tid / 9) % 3, (tid / 3) % 3, tid % 3};
        float acc0 = 0.f, acc1 = 0.f, acc2 = 0.f, acc3 = 0.f;
        #pragma unroll
        for (int m = 0; m < 16; m++) {
            int p = 0, q = 0;
            float wgt = 1.0f / 16.0f;
            #pragma unroll
            for (int w = 0; w < 4; w++) {
                const int opt = (m >> w) & 1;
                const int k = kw[w];
                int a, bb;
                if (k == 0)      { a = opt; bb = opt; }
                else if (k == 1) { a = opt; bb = opt; if (opt) wgt = -wgt; }
                else             { a = opt; bb = 1 - opt; }
                p |= a << (3 - w);
                q |= bb << (3 - w);
            }
            acc0 += wgt * A[0][p * 16 + q];
            acc1 += wgt * A[1][p * 16 + q];
            acc2 += wgt * A[2][p * 16 + q];
            acc3 += wgt * A[3][p * 16 + q];
        }
        g_stage.C[h * NBASIS + tid] = make_float4(acc0, acc1, acc2, acc3);
    }

    if (h == 0) {
        for (int i = tid; i < EMBED * 32; i += blockDim.x) {
            const int e = i >> 5, j = i & 31;          // W[e][j]
            ((float*)&g_stage.Wt4[j][0])[e] = W[i];
        }
        if (tid < EMBED) ((float*)g_stage.b4)[tid] = b[tid];
    }
}

// ---------------------------------------------------------------------------
// Main: 1 thread/token. Coefficients in smem (LDS ~1/cyc/SM vs LDC 0.5/cyc).
// Math packed as f32x2 across output-pairs (q0,q1)/(q2,q3): the pair halves
// are adjacent in every 16B coefficient load, so zero pack overhead.
// ---------------------------------------------------------------------------
__global__ __launch_bounds__(256) void qmha_main(
    const float4* __restrict__ x,    // [tokens][8] float4 (EMBED=32)
    float4*       __restrict__ out,  // [tokens][8] float4
    int tokens)
{
    __shared__ CoefData sD;
    {
        float4* dst = (float4*)&sD;
        const float4* src = (const float4*)&g_stage;
        for (int i = threadIdx.x; i < COEF_F4; i += 256) dst[i] = src[i];
    }
    __syncthreads();

    const int tok = blockIdx.x * 256 + threadIdx.x;
    if (tok >= tokens) return;

    // outr01[e4] holds outputs (4e4+0, 4e4+1); outr23 holds (4e4+2, 4e4+3)
    u64 outr01[8], outr23[8];
    {
        const ulonglong2* bp = (const ulonglong2*)sD.b4;
        #pragma unroll
        for (int e4 = 0; e4 < 8; e4++) {
            ulonglong2 bv = bp[e4];
            outr01[e4] = bv.x;
            outr23[e4] = bv.y;
        }
    }

    #pragma unroll 1
    for (int h = 0; h < NHEADS; h++) {
        const float4 xvh = x[tok * 8 + h];

        float c0, s0, c1, s1, c2, s2, c3, s3;
        __sincosf(xvh.x, &s0, &c0);
        __sincosf(xvh.y, &s1, &c1);
        __sincosf(xvh.z, &s2, &c2);
        __sincosf(xvh.w, &s3, &c3);

        const float A9[9] = {1.f, c1, s1, c0, c0 * c1, c0 * s1, s0, s0 * c1, s0 * s1};
        const float B9[9] = {1.f, c3, s3, c2, c2 * c3, c2 * s3, s2, s2 * c3, s2 * s3};

        u64 adup[9], bdup[9];
        #pragma unroll
        for (int k = 0; k < 9; k++) {
            adup[k] = pack2(A9[k], A9[k]);
            bdup[k] = pack2(B9[k], B9[k]);
        }

        // ev_q = sum_{i,j} A9[i] B9[j] C[h][i*9+j].q, q-pairs packed
        u64 acc01 = 0ull, acc23 = 0ull;
        const ulonglong2* Ch = (const ulonglong2*)&sD.C[h * NBASIS];
        #pragma unroll
        for (int i = 0; i < 9; i++) {
            u64 p01 = 0ull, p23 = 0ull;
            #pragma unroll
            for (int j = 0; j < 9; j++) {
                const ulonglong2 Cv = Ch[i * 9 + j];   // LDS.128 -> 2 reg-pairs
                p01 = fma2(Cv.x, bdup[j], p01);
                p23 = fma2(Cv.y, bdup[j], p23);
            }
            acc01 = fma2(adup[i], p01, acc01);
            acc23 = fma2(adup[i], p23, acc23);
        }

        const float2 ev01 = unpack2(acc01);
        const float2 ev23 = unpack2(acc23);
        const float evq[4] = {ev01.x, ev01.y, ev23.x, ev23.y};

        // fold the 4 expvals into 32 outputs via Wt4 (pairs adjacent in load)
        #pragma unroll
        for (int q = 0; q < 4; q++) {
            const u64 evd = pack2(evq[q], evq[q]);
            const ulonglong2* Wr = (const ulonglong2*)&sD.Wt4[h * 4 + q][0];
            #pragma unroll
            for (int e4 = 0; e4 < 8; e4++) {
                const ulonglong2 wv = Wr[e4];
                outr01[e4] = fma2(evd, wv.x, outr01[e4]);
                outr23[e4] = fma2(evd, wv.y, outr23[e4]);
            }
        }
    }

    ulonglong2* op = (ulonglong2*)(out + tok * 8);
    #pragma unroll
    for (int e4 = 0; e4 < 8; e4++) {
        ulonglong2 v;
        v.x = outr01[e4];   // outputs 4e4+0, 4e4+1
        v.y = outr23[e4];   // outputs 4e4+2, 4e4+3
        op[e4] = v;
    }
}

extern "C" void kernel_launch(void* const* d_in, const int* in_sizes, int n_in,
                              void* d_out, int out_size) {
    const float* x      = (const float*)d_in[0];
    const float* params = (const float*)d_in[1];
    const float* W      = (const float*)d_in[2];
    const float* b      = (const float*)d_in[3];

    const int tokens = in_sizes[0] / EMBED;   // B*S = 131072

    qmha_precompute<<<NHEADS, 256>>>(params, W, b);

    const int threads = 256;
    const int blocks = (tokens + threads - 1) / threads;
    qmha_main<<<blocks, threads>>>((const float4*)x, (float4*)d_out, tokens);
}

// round 4
// speedup vs baseline: 1.0006x; 1.0006x over previous
#include <cuda_runtime.h>

#define NQ      4
#define DIM     16
#define NHEADS  8
#define NLAYERS 2
#define EMBED   32
#define NBASIS  81

typedef unsigned long long u64;

struct CoefData {
    float4 C[NHEADS * NBASIS];   // C[h*81+k]: 4 Z-expval coeffs (q0..q3)
    float4 Wt4[32][8];           // Wt4[j][e4].k = W_out[e4*4+k][j]
    float4 b4[8];
};
__device__ CoefData g_stage;

#define COEF_F4 ((int)(sizeof(CoefData) / 16))

// ---- packed f32x2 helpers ----
__device__ __forceinline__ u64 fma2(u64 a, u64 b, u64 c) {
    u64 d;
    asm("fma.rn.f32x2 %0, %1, %2, %3;" : "=l"(d) : "l"(a), "l"(b), "l"(c));
    return d;
}
__device__ __forceinline__ u64 pack2(float x, float y) {
    u64 d;
    asm("mov.b64 %0, {%1, %2};" : "=l"(d) : "f"(x), "f"(y));
    return d;
}
__device__ __forceinline__ float2 unpack2(u64 v) {
    float2 r;
    asm("mov.b64 {%0, %1}, %2;" : "=f"(r.x), "=f"(r.y) : "l"(v));
    return r;
}

// ---------------------------------------------------------------------------
// Precompute: ONE block, 256 threads, all 8 heads.
// ---------------------------------------------------------------------------
__global__ void qmha_precompute(const float* __restrict__ params,
                                const float* __restrict__ W,
                                const float* __restrict__ b) {
    __shared__ float Ur[NHEADS][DIM][DIM];   // [h][col p][state s]
    __shared__ float Ui[NHEADS][DIM][DIM];
    __shared__ float A[NHEADS][NQ][DIM * DIM];

    const int tid = threadIdx.x;

    // --- Step 1: 128 threads = 8 heads x 16 basis columns ---
    if (tid < NHEADS * DIM) {
        const int h = tid >> 4, col = tid & 15;
        float re[DIM], im[DIM];
        #pragma unroll
        for (int s = 0; s < DIM; s++) { re[s] = 0.f; im[s] = 0.f; }
        re[col] = 1.f;

        const float* ph = params + h * NLAYERS * NQ * 3;

        for (int l = 0; l < NLAYERS; l++) {
            for (int w = 0; w < NQ; w++) {
                const int mask = 1 << (3 - w);
                float tx = ph[(l * NQ + w) * 3 + 0];
                float ty = ph[(l * NQ + w) * 3 + 1];
                float tz = ph[(l * NQ + w) * 3 + 2];
                float cx = cosf(0.5f * tx), sx = sinf(0.5f * tx);
                float cy = cosf(0.5f * ty), sy = sinf(0.5f * ty);
                float cz = cosf(0.5f * tz), sz = sinf(0.5f * tz);
                #pragma unroll
                for (int s0 = 0; s0 < DIM; s0++) {
                    if (s0 & mask) continue;
                    const int s1 = s0 | mask;
                    float r0 = re[s0], i0 = im[s0], r1 = re[s1], i1 = im[s1];
                    // RX
                    float nr0 = cx * r0 + sx * i1;
                    float ni0 = cx * i0 - sx * r1;
                    float nr1 = sx * i0 + cx * r1;
                    float ni1 = -sx * r0 + cx * i1;
                    // RY
                    r0 = nr0; i0 = ni0; r1 = nr1; i1 = ni1;
                    nr0 = cy * r0 - sy * r1;
                    ni0 = cy * i0 - sy * i1;
                    nr1 = sy * r0 + cy * r1;
                    ni1 = sy * i0 + cy * i1;
                    // RZ
                    r0 = nr0; i0 = ni0; r1 = nr1; i1 = ni1;
                    re[s0] = cz * r0 + sz * i0;
                    im[s0] = cz * i0 - sz * r0;
                    re[s1] = cz * r1 - sz * i1;
                    im[s1] = cz * i1 + sz * r1;
                }
            }
            #pragma unroll
            for (int e = 0; e < NQ; e++) {
                const int c = e, t = (e + 1) & 3;
                const int cm = 1 << (3 - c), tm = 1 << (3 - t);
                #pragma unroll
                for (int s = 0; s < DIM; s++) {
                    if ((s & cm) && !(s & tm)) {
                        const int s2 = s | tm;
                        float tr = re[s]; re[s] = re[s2]; re[s2] = tr;
                        float ti = im[s]; im[s] = im[s2]; im[s2] = ti;
                    }
                }
            }
        }
        #pragma unroll
        for (int s = 0; s < DIM; s++) { Ur[h][col][s] = re[s]; Ui[h][col][s] = im[s]; }
    }
    __syncthreads();

    // --- Step 2: A[h][i][p*16+q] ---
    for (int e = tid; e < NHEADS * 256; e += 256) {
        const int h = e >> 8, pq = e & 255;
        const int p = pq >> 4, q = pq & 15;
        float a0 = 0.f, a1 = 0.f, a2 = 0.f, a3 = 0.f;
        #pragma unroll
        for (int s = 0; s < DIM; s++) {
            float rr = Ur[h][p][s] * Ur[h][q][s] + Ui[h][p][s] * Ui[h][q][s];
            a0 += (s & 8) ? -rr : rr;
            a1 += (s & 4) ? -rr : rr;
            a2 += (s & 2) ? -rr : rr;
            a3 += (s & 1) ? -rr : rr;
        }
        A[h][0][pq] = a0; A[h][1][pq] = a1; A[h][2][pq] = a2; A[h][3][pq] = a3;
    }
    __syncthreads();

    // --- Step 3: project onto {1,cos,sin}^4 ---
    for (int e = tid; e < NHEADS * NBASIS; e += 256) {
        const int h = e / NBASIS, k = e % NBASIS;
        int kw[4] = {k / 27, (k / 9) % 3, (k / 3) % 3, k % 3};
        float acc0 = 0.f, acc1 = 0.f, acc2 = 0.f, acc3 = 0.f;
        #pragma unroll
        for (int m = 0; m < 16; m++) {
            int p = 0, q = 0;
            float wgt = 1.0f / 16.0f;
            #pragma unroll
            for (int w = 0; w < 4; w++) {
                const int opt = (m >> w) & 1;
                const int kk = kw[w];
                int a, bb;
                if (kk == 0)      { a = opt; bb = opt; }
                else if (kk == 1) { a = opt; bb = opt; if (opt) wgt = -wgt; }
                else              { a = opt; bb = 1 - opt; }
                p |= a << (3 - w);
                q |= bb << (3 - w);
            }
            acc0 += wgt * A[h][0][p * 16 + q];
            acc1 += wgt * A[h][1][p * 16 + q];
            acc2 += wgt * A[h][2][p * 16 + q];
            acc3 += wgt * A[h][3][p * 16 + q];
        }
        g_stage.C[e] = make_float4(acc0, acc1, acc2, acc3);
    }

    // --- Step 4: pack Wt4 / b4 ---
    for (int i = tid; i < EMBED * 32; i += 256) {
        const int e = i >> 5, j = i & 31;
        ((float*)&g_stage.Wt4[j][0])[e] = W[i];
    }
    if (tid < EMBED) ((float*)g_stage.b4)[tid] = b[tid];
}

// ---------------------------------------------------------------------------
// Main: T=2 tokens/thread sharing every coefficient load; one-wave config
// (64-thread blocks, 7 blocks/SM resident => 448 thr/SM >= 443 needed).
// ---------------------------------------------------------------------------
__global__ __launch_bounds__(64, 7) void qmha_main(
    const float4* __restrict__ x,
    float4*       __restrict__ out,
    int tokens)
{
    __shared__ CoefData sD;
    {
        float4* dst = (float4*)&sD;
        const float4* src = (const float4*)&g_stage;
        for (int i = threadIdx.x; i < COEF_F4; i += 64) dst[i] = src[i];
    }
    __syncthreads();

    const int half = tokens >> 1;
    const int gtid = blockIdx.x * 64 + threadIdx.x;
    if (gtid >= half) return;
    const int t0 = gtid, t1 = gtid + half;

    u64 oA01[8], oA23[8], oB01[8], oB23[8];
    {
        const ulonglong2* bp = (const ulonglong2*)sD.b4;
        #pragma unroll
        for (int e4 = 0; e4 < 8; e4++) {
            const ulonglong2 bv = bp[e4];
            oA01[e4] = bv.x; oA23[e4] = bv.y;
            oB01[e4] = bv.x; oB23[e4] = bv.y;
        }
    }

    #pragma unroll 1
    for (int h = 0; h < NHEADS; h++) {
        const float4 xa = x[t0 * 8 + h];
        const float4 xb = x[t1 * 8 + h];

        float c0a, s0a, c1a, s1a, c2a, s2a, c3a, s3a;
        float c0b, s0b, c1b, s1b, c2b, s2b, c3b, s3b;
        __sincosf(xa.x, &s0a, &c0a); __sincosf(xa.y, &s1a, &c1a);
        __sincosf(xa.z, &s2a, &c2a); __sincosf(xa.w, &s3a, &c3a);
        __sincosf(xb.x, &s0b, &c0b); __sincosf(xb.y, &s1b, &c1b);
        __sincosf(xb.z, &s2b, &c2b); __sincosf(xb.w, &s3b, &c3b);

        // B9 = (1,c3,s3) x (1? ...) = {1, c3, s3, c2, c2c3, c2s3, s2, s2c3, s2s3}
        u64 bdA[9], bdB[9];
        {
            const float B9a[9] = {1.f, c3a, s3a, c2a, c2a * c3a, c2a * s3a,
                                  s2a, s2a * c3a, s2a * s3a};
            const float B9b[9] = {1.f, c3b, s3b, c2b, c2b * c3b, c2b * s3b,
                                  s2b, s2b * c3b, s2b * s3b};
            #pragma unroll
            for (int j = 0; j < 9; j++) {
                bdA[j] = pack2(B9a[j], B9a[j]);
                bdB[j] = pack2(B9b[j], B9b[j]);
            }
        }

        u64 accA01 = 0ull, accA23 = 0ull, accB01 = 0ull, accB23 = 0ull;
        const ulonglong2* Ch = (const ulonglong2*)&sD.C[h * NBASIS];

        // A factors rebuilt per-i from 4 values (saves registers):
        // A9[i] = f0[i/3] * f1[i%3], f0=(1,c0,s0), f1=(1,c1,s1)
        const float f0a[3] = {1.f, c0a, s0a}, f1a[3] = {1.f, c1a, s1a};
        const float f0b[3] = {1.f, c0b, s0b}, f1b[3] = {1.f, c1b, s1b};

        #pragma unroll
        for (int i = 0; i < 9; i++) {
            const float aA = f0a[i / 3] * f1a[i % 3];
            const float aB = f0b[i / 3] * f1b[i % 3];
            const u64 adA = pack2(aA, aA);
            const u64 adB = pack2(aB, aB);

            u64 pA01 = 0ull, pA23 = 0ull, pB01 = 0ull, pB23 = 0ull;
            #pragma unroll
            for (int j = 0; j < 9; j++) {
                const ulonglong2 Cv = Ch[i * 9 + j];   // shared: 1 load, 4 fma2
                pA01 = fma2(Cv.x, bdA[j], pA01);
                pA23 = fma2(Cv.y, bdA[j], pA23);
                pB01 = fma2(Cv.x, bdB[j], pB01);
                pB23 = fma2(Cv.y, bdB[j], pB23);
            }
            accA01 = fma2(adA, pA01, accA01);
            accA23 = fma2(adA, pA23, accA23);
            accB01 = fma2(adB, pB01, accB01);
            accB23 = fma2(adB, pB23, accB23);
        }

        const float2 evA01 = unpack2(accA01), evA23 = unpack2(accA23);
        const float2 evB01 = unpack2(accB01), evB23 = unpack2(accB23);
        const float evqA[4] = {evA01.x, evA01.y, evA23.x, evA23.y};
        const float evqB[4] = {evB01.x, evB01.y, evB23.x, evB23.y};

        #pragma unroll
        for (int q = 0; q < 4; q++) {
            const u64 edA = pack2(evqA[q], evqA[q]);
            const u64 edB = pack2(evqB[q], evqB[q]);
            const ulonglong2* Wr = (const ulonglong2*)&sD.Wt4[h * 4 + q][0];
            #pragma unroll
            for (int e4 = 0; e4 < 8; e4++) {
                const ulonglong2 wv = Wr[e4];          // shared: 1 load, 4 fma2
                oA01[e4] = fma2(edA, wv.x, oA01[e4]);
                oA23[e4] = fma2(edA, wv.y, oA23[e4]);
                oB01[e4] = fma2(edB, wv.x, oB01[e4]);
                oB23[e4] = fma2(edB, wv.y, oB23[e4]);
            }
        }
    }

    ulonglong2* opA = (ulonglong2*)(out + t0 * 8);
    ulonglong2* opB = (ulonglong2*)(out + t1 * 8);
    #pragma unroll
    for (int e4 = 0; e4 < 8; e4++) {
        ulonglong2 va; va.x = oA01[e4]; va.y = oA23[e4];
        ulonglong2 vb; vb.x = oB01[e4]; vb.y = oB23[e4];
        opA[e4] = va;
        opB[e4] = vb;
    }
}

extern "C" void kernel_launch(void* const* d_in, const int* in_sizes, int n_in,
                              void* d_out, int out_size) {
    const float* x      = (const float*)d_in[0];
    const float* params = (const float*)d_in[1];
    const float* W      = (const float*)d_in[2];
    const float* b      = (const float*)d_in[3];

    const int tokens = in_sizes[0] / EMBED;   // 131072
    const int half = tokens >> 1;             // 65536 threads

    qmha_precompute<<<1, 256>>>(params, W, b);

    const int threads = 64;
    const int blocks = (half + threads - 1) / threads;   // 1024
    qmha_main<<<blocks, threads>>>((const float4*)x, (float4*)d_out, tokens);
}

// round 6
// speedup vs baseline: 1.0054x; 1.0048x over previous
#include <cuda_runtime.h>

#define NQ      4
#define DIM     16
#define NHEADS  8
#define NLAYERS 2
#define EMBED   32
#define NBASIS  81

typedef unsigned long long u64;

struct CoefData {
    float4 C[NHEADS * NBASIS];   // C[h*81+k]: 4 Z-expval coeffs (q0..q3)
    float4 Wt4[32][8];           // Wt4[j][e4].k = W_out[e4*4+k][j]
    float4 b4[8];
};
__device__ CoefData g_stage;

#define COEF_F4 ((int)(sizeof(CoefData) / 16))

// ---- packed f32x2 helpers (PTX-only; ptxas never auto-fuses FFMA2) ----
__device__ __forceinline__ u64 fma2(u64 a, u64 b, u64 c) {
    u64 d;
    asm("fma.rn.f32x2 %0, %1, %2, %3;" : "=l"(d) : "l"(a), "l"(b), "l"(c));
    return d;
}
__device__ __forceinline__ u64 pack2(float x, float y) {
    u64 d;
    asm("mov.b64 %0, {%1, %2};" : "=l"(d) : "f"(x), "f"(y));
    return d;
}
__device__ __forceinline__ float2 unpack2(u64 v) {
    float2 r;
    asm("mov.b64 {%0, %1}, %2;" : "=f"(r.x), "=f"(r.y) : "l"(v));
    return r;
}

// ---------------------------------------------------------------------------
// Precompute: ONE block, 256 threads, all 8 heads.
// ---------------------------------------------------------------------------
__global__ void qmha_precompute(const float* __restrict__ params,
                                const float* __restrict__ W,
                                const float* __restrict__ b) {
    __shared__ float Ur[NHEADS][DIM][DIM];   // [h][col p][state s]
    __shared__ float Ui[NHEADS][DIM][DIM];
    __shared__ float A[NHEADS][NQ][DIM * DIM];

    const int tid = threadIdx.x;

    // --- Step 1: 128 threads = 8 heads x 16 basis columns ---
    if (tid < NHEADS * DIM) {
        const int h = tid >> 4, col = tid & 15;
        float re[DIM], im[DIM];
        #pragma unroll
        for (int s = 0; s < DIM; s++) { re[s] = 0.f; im[s] = 0.f; }
        re[col] = 1.f;

        const float* ph = params + h * NLAYERS * NQ * 3;

        for (int l = 0; l < NLAYERS; l++) {
            for (int w = 0; w < NQ; w++) {
                const int mask = 1 << (3 - w);
                float tx = ph[(l * NQ + w) * 3 + 0];
                float ty = ph[(l * NQ + w) * 3 + 1];
                float tz = ph[(l * NQ + w) * 3 + 2];
                float cx = cosf(0.5f * tx), sx = sinf(0.5f * tx);
                float cy = cosf(0.5f * ty), sy = sinf(0.5f * ty);
                float cz = cosf(0.5f * tz), sz = sinf(0.5f * tz);
                #pragma unroll
                for (int s0 = 0; s0 < DIM; s0++) {
                    if (s0 & mask) continue;
                    const int s1 = s0 | mask;
                    float r0 = re[s0], i0 = im[s0], r1 = re[s1], i1 = im[s1];
                    // RX
                    float nr0 = cx * r0 + sx * i1;
                    float ni0 = cx * i0 - sx * r1;
                    float nr1 = sx * i0 + cx * r1;
                    float ni1 = -sx * r0 + cx * i1;
                    // RY
                    r0 = nr0; i0 = ni0; r1 = nr1; i1 = ni1;
                    nr0 = cy * r0 - sy * r1;
                    ni0 = cy * i0 - sy * i1;
                    nr1 = sy * r0 + cy * r1;
                    ni1 = sy * i0 + cy * i1;
                    // RZ
                    r0 = nr0; i0 = ni0; r1 = nr1; i1 = ni1;
                    re[s0] = cz * r0 + sz * i0;
                    im[s0] = cz * i0 - sz * r0;
                    re[s1] = cz * r1 - sz * i1;
                    im[s1] = cz * i1 + sz * r1;
                }
            }
            #pragma unroll
            for (int e = 0; e < NQ; e++) {
                const int c = e, t = (e + 1) & 3;
                const int cm = 1 << (3 - c), tm = 1 << (3 - t);
                #pragma unroll
                for (int s = 0; s < DIM; s++) {
                    if ((s & cm) && !(s & tm)) {
                        const int s2 = s | tm;
                        float tr = re[s]; re[s] = re[s2]; re[s2] = tr;
                        float ti = im[s]; im[s] = im[s2]; im[s2] = ti;
                    }
                }
            }
        }
        #pragma unroll
        for (int s = 0; s < DIM; s++) { Ur[h][col][s] = re[s]; Ui[h][col][s] = im[s]; }
    }
    __syncthreads();

    // --- Step 2: A[h][i][p*16+q] = sum_s z_i(s) Re(conj(U[s,p]) U[s,q]) ---
    for (int e = tid; e < NHEADS * 256; e += 256) {
        const int h = e >> 8, pq = e & 255;
        const int p = pq >> 4, q = pq & 15;
        float a0 = 0.f, a1 = 0.f, a2 = 0.f, a3 = 0.f;
        #pragma unroll
        for (int s = 0; s < DIM; s++) {
            float rr = Ur[h][p][s] * Ur[h][q][s] + Ui[h][p][s] * Ui[h][q][s];
            a0 += (s & 8) ? -rr : rr;
            a1 += (s & 4) ? -rr : rr;
            a2 += (s & 2) ? -rr : rr;
            a3 += (s & 1) ? -rr : rr;
        }
        A[h][0][pq] = a0; A[h][1][pq] = a1; A[h][2][pq] = a2; A[h][3][pq] = a3;
    }
    __syncthreads();

    // --- Step 3: project onto {1,cos,sin}^4 basis ---
    for (int e = tid; e < NHEADS * NBASIS; e += 256) {
        const int h = e / NBASIS, k = e % NBASIS;
        int kw[4] = {k / 27, (k / 9) % 3, (k / 3) % 3, k % 3};
        float acc0 = 0.f, acc1 = 0.f, acc2 = 0.f, acc3 = 0.f;
        #pragma unroll
        for (int m = 0; m < 16; m++) {
            int p = 0, q = 0;
            float wgt = 1.0f / 16.0f;
            #pragma unroll
            for (int w = 0; w < 4; w++) {
                const int opt = (m >> w) & 1;
                const int kk = kw[w];
                int a, bb;
                if (kk == 0)      { a = opt; bb = opt; }
                else if (kk == 1) { a = opt; bb = opt; if (opt) wgt = -wgt; }
                else              { a = opt; bb = 1 - opt; }
                p |= a << (3 - w);
                q |= bb << (3 - w);
            }
            acc0 += wgt * A[h][0][p * 16 + q];
            acc1 += wgt * A[h][1][p * 16 + q];
            acc2 += wgt * A[h][2][p * 16 + q];
            acc3 += wgt * A[h][3][p * 16 + q];
        }
        g_stage.C[e] = make_float4(acc0, acc1, acc2, acc3);
    }

    // --- Step 4: pack Wt4 / b4 ---
    for (int i = tid; i < EMBED * 32; i += 256) {
        const int e = i >> 5, j = i & 31;
        ((float*)&g_stage.Wt4[j][0])[e] = W[i];
    }
    if (tid < EMBED) ((float*)g_stage.b4)[tid] = b[tid];
}

// ---------------------------------------------------------------------------
// Main: T=2 tokens/thread sharing every coefficient load; one-wave config
// (64-thread blocks, 7 blocks/SM resident => 448 thr/SM >= 443 needed).
// ---------------------------------------------------------------------------
__global__ __launch_bounds__(64, 7) void qmha_main(
    const float4* __restrict__ x,
    float4*       __restrict__ out,
    int tokens)
{
    __shared__ CoefData sD;
    {
        float4* dst = (float4*)&sD;
        const float4* src = (const float4*)&g_stage;
        for (int i = threadIdx.x; i < COEF_F4; i += 64) dst[i] = src[i];
    }
    __syncthreads();

    const int half = tokens >> 1;
    const int gtid = blockIdx.x * 64 + threadIdx.x;
    if (gtid >= half) return;
    const int t0 = gtid, t1 = gtid + half;

    u64 oA01[8], oA23[8], oB01[8], oB23[8];
    {
        const ulonglong2* bp = (const ulonglong2*)sD.b4;
        #pragma unroll
        for (int e4 = 0; e4 < 8; e4++) {
            const ulonglong2 bv = bp[e4];
            oA01[e4] = bv.x; oA23[e4] = bv.y;
            oB01[e4] = bv.x; oB23[e4] = bv.y;
        }
    }

    #pragma unroll 1
    for (int h = 0; h < NHEADS; h++) {
        const float4 xa = x[t0 * 8 + h];
        const float4 xb = x[t1 * 8 + h];

        float c0a, s0a, c1a, s1a, c2a, s2a, c3a, s3a;
        float c0b, s0b, c1b, s1b, c2b, s2b, c3b, s3b;
        __sincosf(xa.x, &s0a, &c0a); __sincosf(xa.y, &s1a, &c1a);
        __sincosf(xa.z, &s2a, &c2a); __sincosf(xa.w, &s3a, &c3a);
        __sincosf(xb.x, &s0b, &c0b); __sincosf(xb.y, &s1b, &c1b);
        __sincosf(xb.z, &s2b, &c2b); __sincosf(xb.w, &s3b, &c3b);

        // B9 = {1, c3, s3, c2, c2c3, c2s3, s2, s2c3, s2s3}, packed dup
        u64 bdA[9], bdB[9];
        {
            const float B9a[9] = {1.f, c3a, s3a, c2a, c2a * c3a, c2a * s3a,
                                  s2a, s2a * c3a, s2a * s3a};
            const float B9b[9] = {1.f, c3b, s3b, c2b, c2b * c3b, c2b * s3b,
                                  s2b, s2b * c3b, s2b * s3b};
            #pragma unroll
            for (int j = 0; j < 9; j++) {
                bdA[j] = pack2(B9a[j], B9a[j]);
                bdB[j] = pack2(B9b[j], B9b[j]);
            }
        }

        u64 accA01 = 0ull, accA23 = 0ull, accB01 = 0ull, accB23 = 0ull;
        const ulonglong2* Ch = (const ulonglong2*)&sD.C[h * NBASIS];

        // A9[i] = f0[i/3] * f1[i%3], rebuilt per-i (register saver)
        const float f0a[3] = {1.f, c0a, s0a}, f1a[3] = {1.f, c1a, s1a};
        const float f0b[3] = {1.f, c0b, s0b}, f1b[3] = {1.f, c1b, s1b};

        #pragma unroll
        for (int i = 0; i < 9; i++) {
            const float aA = f0a[i / 3] * f1a[i % 3];
            const float aB = f0b[i / 3] * f1b[i % 3];
            const u64 adA = pack2(aA, aA);
            const u64 adB = pack2(aB, aB);

            u64 pA01 = 0ull, pA23 = 0ull, pB01 = 0ull, pB23 = 0ull;
            #pragma unroll
            for (int j = 0; j < 9; j++) {
                const ulonglong2 Cv = Ch[i * 9 + j];   // 1 LDS.128 feeds 4 fma2
                pA01 = fma2(Cv.x, bdA[j], pA01);
                pA23 = fma2(Cv.y, bdA[j], pA23);
                pB01 = fma2(Cv.x, bdB[j], pB01);
                pB23 = fma2(Cv.y, bdB[j], pB23);
            }
            accA01 = fma2(adA, pA01, accA01);
            accA23 = fma2(adA, pA23, accA23);
            accB01 = fma2(adB, pB01, accB01);
            accB23 = fma2(adB, pB23, accB23);
        }

        const float2 evA01 = unpack2(accA01), evA23 = unpack2(accA23);
        const float2 evB01 = unpack2(accB01), evB23 = unpack2(accB23);
        const float evqA[4] = {evA01.x, evA01.y, evA23.x, evA23.y};
        const float evqB[4] = {evB01.x, evB01.y, evB23.x, evB23.y};

        #pragma unroll
        for (int q = 0; q < 4; q++) {
            const u64 edA = pack2(evqA[q], evqA[q]);
            const u64 edB = pack2(evqB[q], evqB[q]);
            const ulonglong2* Wr = (const ulonglong2*)&sD.Wt4[h * 4 + q][0];
            #pragma unroll
            for (int e4 = 0; e4 < 8; e4++) {
                const ulonglong2 wv = Wr[e4];          // 1 LDS.128 feeds 4 fma2
                oA01[e4] = fma2(edA, wv.x, oA01[e4]);
                oA23[e4] = fma2(edA, wv.y, oA23[e4]);
                oB01[e4] = fma2(edB, wv.x, oB01[e4]);
                oB23[e4] = fma2(edB, wv.y, oB23[e4]);
            }
        }
    }

    ulonglong2* opA = (ulonglong2*)(out + t0 * 8);
    ulonglong2* opB = (ulonglong2*)(out + t1 * 8);
    #pragma unroll
    for (int e4 = 0; e4 < 8; e4++) {
        ulonglong2 va; va.x = oA01[e4]; va.y = oA23[e4];
        ulonglong2 vb; vb.x = oB01[e4]; vb.y = oB23[e4];
        opA[e4] = va;
        opB[e4] = vb;
    }
}

extern "C" void kernel_launch(void* const* d_in, const int* in_sizes, int n_in,
                              void* d_out, int out_size) {
    const float* x      = (const float*)d_in[0];
    const float* params = (const float*)d_in[1];
    const float* W      = (const float*)d_in[2];
    const float* b      = (const float*)d_in[3];

    const int tokens = in_sizes[0] / EMBED;   // 131072
    const int half = tokens >> 1;             // 65536 threads

    qmha_precompute<<<1, 256>>>(params, W, b);

    const int threads = 64;
    const int blocks = (half + threads - 1) / threads;   // 1024
    qmha_main<<<blocks, threads>>>((const float4*)x, (float4*)d_out, tokens);
}

// round 7
// speedup vs baseline: 1.1972x; 1.1908x over previous
#include <cuda_runtime.h>

#define NQ      4
#define DIM     16
#define NHEADS  8
#define NLAYERS 2
#define EMBED   32
#define NBASIS  81

typedef unsigned long long u64;

struct CoefData {
    float4 C[NHEADS * NBASIS];   // C[h*81+k]: 4 Z-expval coeffs (q0..q3)
    float4 Wt4[32][8];           // Wt4[j][e4].k = W_out[e4*4+k][j]
    float4 b4[8];
};
__device__ CoefData g_stage;

#define COEF_F4 ((int)(sizeof(CoefData) / 16))

// ---- packed f32x2 helpers (PTX-only; ptxas never auto-fuses FFMA2) ----
__device__ __forceinline__ u64 fma2(u64 a, u64 b, u64 c) {
    u64 d;
    asm("fma.rn.f32x2 %0, %1, %2, %3;" : "=l"(d) : "l"(a), "l"(b), "l"(c));
    return d;
}
__device__ __forceinline__ u64 pack2(float x, float y) {
    u64 d;
    asm("mov.b64 %0, {%1, %2};" : "=l"(d) : "f"(x), "f"(y));
    return d;
}
__device__ __forceinline__ float2 unpack2(u64 v) {
    float2 r;
    asm("mov.b64 {%0, %1}, %2;" : "=f"(r.x), "=f"(r.y) : "l"(v));
    return r;
}

// ---------------------------------------------------------------------------
// Precompute: grid=8 (one head per block, 256 thr) — the R2-validated shape
// (~2us). Block 0 additionally packs Wt4/b4.
// ---------------------------------------------------------------------------
__global__ void qmha_precompute(const float* __restrict__ params,
                                const float* __restrict__ W,
                                const float* __restrict__ b) {
    __shared__ float Ur[DIM][DIM];   // [column p][state s]
    __shared__ float Ui[DIM][DIM];
    __shared__ float A[NQ][DIM * DIM];

    const int h   = blockIdx.x;
    const int tid = threadIdx.x;

    // --- Step 1: 16 threads simulate the 16 basis columns of U_h ---
    if (tid < DIM) {
        float re[DIM], im[DIM];
        #pragma unroll
        for (int s = 0; s < DIM; s++) { re[s] = 0.f; im[s] = 0.f; }
        re[tid] = 1.f;

        const float* ph = params + h * NLAYERS * NQ * 3;

        for (int l = 0; l < NLAYERS; l++) {
            for (int w = 0; w < NQ; w++) {
                const int mask = 1 << (3 - w);
                float tx = ph[(l * NQ + w) * 3 + 0];
                float ty = ph[(l * NQ + w) * 3 + 1];
                float tz = ph[(l * NQ + w) * 3 + 2];
                float cx = cosf(0.5f * tx), sx = sinf(0.5f * tx);
                float cy = cosf(0.5f * ty), sy = sinf(0.5f * ty);
                float cz = cosf(0.5f * tz), sz = sinf(0.5f * tz);
                #pragma unroll
                for (int s0 = 0; s0 < DIM; s0++) {
                    if (s0 & mask) continue;
                    const int s1 = s0 | mask;
                    float r0 = re[s0], i0 = im[s0], r1 = re[s1], i1 = im[s1];
                    // RX
                    float nr0 = cx * r0 + sx * i1;
                    float ni0 = cx * i0 - sx * r1;
                    float nr1 = sx * i0 + cx * r1;
                    float ni1 = -sx * r0 + cx * i1;
                    // RY
                    r0 = nr0; i0 = ni0; r1 = nr1; i1 = ni1;
                    nr0 = cy * r0 - sy * r1;
                    ni0 = cy * i0 - sy * i1;
                    nr1 = sy * r0 + cy * r1;
                    ni1 = sy * i0 + cy * i1;
                    // RZ
                    r0 = nr0; i0 = ni0; r1 = nr1; i1 = ni1;
                    re[s0] = cz * r0 + sz * i0;
                    im[s0] = cz * i0 - sz * r0;
                    re[s1] = cz * r1 - sz * i1;
                    im[s1] = cz * i1 + sz * r1;
                }
            }
            #pragma unroll
            for (int e = 0; e < NQ; e++) {
                const int c = e, t = (e + 1) & 3;
                const int cm = 1 << (3 - c), tm = 1 << (3 - t);
                #pragma unroll
                for (int s = 0; s < DIM; s++) {
                    if ((s & cm) && !(s & tm)) {
                        const int s2 = s | tm;
                        float tr = re[s]; re[s] = re[s2]; re[s2] = tr;
                        float ti = im[s]; im[s] = im[s2]; im[s2] = ti;
                    }
                }
            }
        }
        #pragma unroll
        for (int s = 0; s < DIM; s++) { Ur[tid][s] = re[s]; Ui[tid][s] = im[s]; }
    }
    __syncthreads();

    // --- Step 2: A_i[p][q] = sum_s z_i(s) Re(conj(U[s,p]) U[s,q]) ---
    {
        const int p = tid >> 4, q = tid & 15;
        float a0 = 0.f, a1 = 0.f, a2 = 0.f, a3 = 0.f;
        #pragma unroll
        for (int s = 0; s < DIM; s++) {
            float rr = Ur[p][s] * Ur[q][s] + Ui[p][s] * Ui[q][s];
            a0 += (s & 8) ? -rr : rr;
            a1 += (s & 4) ? -rr : rr;
            a2 += (s & 2) ? -rr : rr;
            a3 += (s & 1) ? -rr : rr;
        }
        A[0][tid] = a0; A[1][tid] = a1; A[2][tid] = a2; A[3][tid] = a3;
    }
    __syncthreads();

    // --- Step 3: project onto {1,cos,sin}^4 basis ---
    if (tid < NBASIS) {
        int kw[4] = {tid / 27, (tid / 9) % 3, (tid / 3) % 3, tid % 3};
        float acc0 = 0.f, acc1 = 0.f, acc2 = 0.f, acc3 = 0.f;
        #pragma unroll
        for (int m = 0; m < 16; m++) {
            int p = 0, q = 0;
            float wgt = 1.0f / 16.0f;
            #pragma unroll
            for (int w = 0; w < 4; w++) {
                const int opt = (m >> w) & 1;
                const int kk = kw[w];
                int a, bb;
                if (kk == 0)      { a = opt; bb = opt; }
                else if (kk == 1) { a = opt; bb = opt; if (opt) wgt = -wgt; }
                else              { a = opt; bb = 1 - opt; }
                p |= a << (3 - w);
                q |= bb << (3 - w);
            }
            acc0 += wgt * A[0][p * 16 + q];
            acc1 += wgt * A[1][p * 16 + q];
            acc2 += wgt * A[2][p * 16 + q];
            acc3 += wgt * A[3][p * 16 + q];
        }
        g_stage.C[h * NBASIS + tid] = make_float4(acc0, acc1, acc2, acc3);
    }

    // --- Block 0: pack Wt4 / b4 ---
    if (h == 0) {
        for (int i = tid; i < EMBED * 32; i += 256) {
            const int e = i >> 5, j = i & 31;
            ((float*)&g_stage.Wt4[j][0])[e] = W[i];
        }
        if (tid < EMBED) ((float*)g_stage.b4)[tid] = b[tid];
    }
}

// ---------------------------------------------------------------------------
// Main: T=2 tokens/thread sharing every coefficient load.
// 128-thr blocks, launch_bounds(128,4): reg cap 128 (= natural usage),
// 512 thr/SM resident, grid 512 blocks <= 592 resident => ONE wave.
// ---------------------------------------------------------------------------
__global__ __launch_bounds__(128, 4) void qmha_main(
    const float4* __restrict__ x,
    float4*       __restrict__ out,
    int tokens)
{
    __shared__ CoefData sD;
    {
        float4* dst = (float4*)&sD;
        const float4* src = (const float4*)&g_stage;
        for (int i = threadIdx.x; i < COEF_F4; i += 128) dst[i] = src[i];
    }
    __syncthreads();

    const int half = tokens >> 1;
    const int gtid = blockIdx.x * 128 + threadIdx.x;
    if (gtid >= half) return;
    const int t0 = gtid, t1 = gtid + half;

    u64 oA01[8], oA23[8], oB01[8], oB23[8];
    {
        const ulonglong2* bp = (const ulonglong2*)sD.b4;
        #pragma unroll
        for (int e4 = 0; e4 < 8; e4++) {
            const ulonglong2 bv = bp[e4];
            oA01[e4] = bv.x; oA23[e4] = bv.y;
            oB01[e4] = bv.x; oB23[e4] = bv.y;
        }
    }

    #pragma unroll 1
    for (int h = 0; h < NHEADS; h++) {
        const float4 xa = x[t0 * 8 + h];
        const float4 xb = x[t1 * 8 + h];

        float c0a, s0a, c1a, s1a, c2a, s2a, c3a, s3a;
        float c0b, s0b, c1b, s1b, c2b, s2b, c3b, s3b;
        __sincosf(xa.x, &s0a, &c0a); __sincosf(xa.y, &s1a, &c1a);
        __sincosf(xa.z, &s2a, &c2a); __sincosf(xa.w, &s3a, &c3a);
        __sincosf(xb.x, &s0b, &c0b); __sincosf(xb.y, &s1b, &c1b);
        __sincosf(xb.z, &s2b, &c2b); __sincosf(xb.w, &s3b, &c3b);

        // B9 = {1, c3, s3, c2, c2c3, c2s3, s2, s2c3, s2s3}, packed dup
        u64 bdA[9], bdB[9];
        {
            const float B9a[9] = {1.f, c3a, s3a, c2a, c2a * c3a, c2a * s3a,
                                  s2a, s2a * c3a, s2a * s3a};
            const float B9b[9] = {1.f, c3b, s3b, c2b, c2b * c3b, c2b * s3b,
                                  s2b, s2b * c3b, s2b * s3b};
            #pragma unroll
            for (int j = 0; j < 9; j++) {
                bdA[j] = pack2(B9a[j], B9a[j]);
                bdB[j] = pack2(B9b[j], B9b[j]);
            }
        }

        u64 accA01 = 0ull, accA23 = 0ull, accB01 = 0ull, accB23 = 0ull;
        const ulonglong2* Ch = (const ulonglong2*)&sD.C[h * NBASIS];

        // A9[i] = f0[i/3] * f1[i%3], rebuilt per-i (register saver)
        const float f0a[3] = {1.f, c0a, s0a}, f1a[3] = {1.f, c1a, s1a};
        const float f0b[3] = {1.f, c0b, s0b}, f1b[3] = {1.f, c1b, s1b};

        #pragma unroll
        for (int i = 0; i < 9; i++) {
            const float aA = f0a[i / 3] * f1a[i % 3];
            const float aB = f0b[i / 3] * f1b[i % 3];
            const u64 adA = pack2(aA, aA);
            const u64 adB = pack2(aB, aB);

            u64 pA01 = 0ull, pA23 = 0ull, pB01 = 0ull, pB23 = 0ull;
            #pragma unroll
            for (int j = 0; j < 9; j++) {
                const ulonglong2 Cv = Ch[i * 9 + j];   // 1 LDS.128 feeds 4 fma2
                pA01 = fma2(Cv.x, bdA[j], pA01);
                pA23 = fma2(Cv.y, bdA[j], pA23);
                pB01 = fma2(Cv.x, bdB[j], pB01);
                pB23 = fma2(Cv.y, bdB[j], pB23);
            }
            accA01 = fma2(adA, pA01, accA01);
            accA23 = fma2(adA, pA23, accA23);
            accB01 = fma2(adB, pB01, accB01);
            accB23 = fma2(adB, pB23, accB23);
        }

        const float2 evA01 = unpack2(accA01), evA23 = unpack2(accA23);
        const float2 evB01 = unpack2(accB01), evB23 = unpack2(accB23);
        const float evqA[4] = {evA01.x, evA01.y, evA23.x, evA23.y};
        const float evqB[4] = {evB01.x, evB01.y, evB23.x, evB23.y};

        #pragma unroll
        for (int q = 0; q < 4; q++) {
            const u64 edA = pack2(evqA[q], evqA[q]);
            const u64 edB = pack2(evqB[q], evqB[q]);
            const ulonglong2* Wr = (const ulonglong2*)&sD.Wt4[h * 4 + q][0];
            #pragma unroll
            for (int e4 = 0; e4 < 8; e4++) {
                const ulonglong2 wv = Wr[e4];          // 1 LDS.128 feeds 4 fma2
                oA01[e4] = fma2(edA, wv.x, oA01[e4]);
                oA23[e4] = fma2(edA, wv.y, oA23[e4]);
                oB01[e4] = fma2(edB, wv.x, oB01[e4]);
                oB23[e4] = fma2(edB, wv.y, oB23[e4]);
            }
        }
    }

    ulonglong2* opA = (ulonglong2*)(out + t0 * 8);
    ulonglong2* opB = (ulonglong2*)(out + t1 * 8);
    #pragma unroll
    for (int e4 = 0; e4 < 8; e4++) {
        ulonglong2 va; va.x = oA01[e4]; va.y = oA23[e4];
        ulonglong2 vb; vb.x = oB01[e4]; vb.y = oB23[e4];
        opA[e4] = va;
        opB[e4] = vb;
    }
}

extern "C" void kernel_launch(void* const* d_in, const int* in_sizes, int n_in,
                              void* d_out, int out_size) {
    const float* x      = (const float*)d_in[0];
    const float* params = (const float*)d_in[1];
    const float* W      = (const float*)d_in[2];
    const float* b      = (const float*)d_in[3];

    const int tokens = in_sizes[0] / EMBED;   // 131072
    const int half = tokens >> 1;             // 65536 threads

    qmha_precompute<<<NHEADS, 256>>>(params, W, b);

    const int threads = 128;
    const int blocks = (half + threads - 1) / threads;   // 512
    qmha_main<<<blocks, threads>>>((const float4*)x, (float4*)d_out, tokens);
}

// round 8
// speedup vs baseline: 1.2532x; 1.0468x over previous
#include <cuda_runtime.h>

#define NQ      4
#define DIM     16
#define NHEADS  8
#define NLAYERS 2
#define EMBED   32
#define NBASIS  81

typedef unsigned long long u64;

struct CoefData {
    float4 C[NHEADS * NBASIS];   // C[h*81+k]: 4 Z-expval coeffs (q0..q3)
    float4 Wt4[32][8];           // Wt4[j][e4].k = W_out[e4*4+k][j]
    float4 b4[8];
};
__device__ CoefData g_stage;

#define COEF_F4 ((int)(sizeof(CoefData) / 16))

// ---- packed f32x2 helpers (PTX-only; ptxas never auto-fuses FFMA2) ----
__device__ __forceinline__ u64 fma2(u64 a, u64 b, u64 c) {
    u64 d;
    asm("fma.rn.f32x2 %0, %1, %2, %3;" : "=l"(d) : "l"(a), "l"(b), "l"(c));
    return d;
}
__device__ __forceinline__ u64 pack2(float x, float y) {
    u64 d;
    asm("mov.b64 %0, {%1, %2};" : "=l"(d) : "f"(x), "f"(y));
    return d;
}
__device__ __forceinline__ float2 unpack2(u64 v) {
    float2 r;
    asm("mov.b64 {%0, %1}, %2;" : "=f"(r.x), "=f"(r.y) : "l"(v));
    return r;
}

// ---------------------------------------------------------------------------
// Precompute: grid=8 (one head per block). Gate sincos staged in PARALLEL via
// __sincosf (MUFU) — removes ~96 serial libm sinf/cosf calls per block that
// dominated the non-main time.
// ---------------------------------------------------------------------------
__global__ void qmha_precompute(const float* __restrict__ params,
                                const float* __restrict__ W,
                                const float* __restrict__ b) {
    __shared__ float Ur[DIM][DIM];   // [column p][state s]
    __shared__ float Ui[DIM][DIM];
    __shared__ float A[NQ][DIM * DIM];
    __shared__ float gc[NLAYERS * NQ * 3];   // cos(theta/2) per gate angle
    __shared__ float gs[NLAYERS * NQ * 3];   // sin(theta/2)

    const int h   = blockIdx.x;
    const int tid = threadIdx.x;

    // --- Step 0: parallel sincos staging (24 angles) ---
    if (tid < NLAYERS * NQ * 3) {
        const float th = params[h * NLAYERS * NQ * 3 + tid];
        float s, c;
        __sincosf(0.5f * th, &s, &c);
        gc[tid] = c;
        gs[tid] = s;
    }
    __syncthreads();

    // --- Step 1: 16 threads simulate the 16 basis columns of U_h ---
    if (tid < DIM) {
        float re[DIM], im[DIM];
        #pragma unroll
        for (int s = 0; s < DIM; s++) { re[s] = 0.f; im[s] = 0.f; }
        re[tid] = 1.f;

        for (int l = 0; l < NLAYERS; l++) {
            for (int w = 0; w < NQ; w++) {
                const int mask = 1 << (3 - w);
                const int gi = (l * NQ + w) * 3;
                const float cx = gc[gi + 0], sx = gs[gi + 0];
                const float cy = gc[gi + 1], sy = gs[gi + 1];
                const float cz = gc[gi + 2], sz = gs[gi + 2];
                #pragma unroll
                for (int s0 = 0; s0 < DIM; s0++) {
                    if (s0 & mask) continue;
                    const int s1 = s0 | mask;
                    float r0 = re[s0], i0 = im[s0], r1 = re[s1], i1 = im[s1];
                    // RX
                    float nr0 = cx * r0 + sx * i1;
                    float ni0 = cx * i0 - sx * r1;
                    float nr1 = sx * i0 + cx * r1;
                    float ni1 = -sx * r0 + cx * i1;
                    // RY
                    r0 = nr0; i0 = ni0; r1 = nr1; i1 = ni1;
                    nr0 = cy * r0 - sy * r1;
                    ni0 = cy * i0 - sy * i1;
                    nr1 = sy * r0 + cy * r1;
                    ni1 = sy * i0 + cy * i1;
                    // RZ
                    r0 = nr0; i0 = ni0; r1 = nr1; i1 = ni1;
                    re[s0] = cz * r0 + sz * i0;
                    im[s0] = cz * i0 - sz * r0;
                    re[s1] = cz * r1 - sz * i1;
                    im[s1] = cz * i1 + sz * r1;
                }
            }
            #pragma unroll
            for (int e = 0; e < NQ; e++) {
                const int c = e, t = (e + 1) & 3;
                const int cm = 1 << (3 - c), tm = 1 << (3 - t);
                #pragma unroll
                for (int s = 0; s < DIM; s++) {
                    if ((s & cm) && !(s & tm)) {
                        const int s2 = s | tm;
                        float tr = re[s]; re[s] = re[s2]; re[s2] = tr;
                        float ti = im[s]; im[s] = im[s2]; im[s2] = ti;
                    }
                }
            }
        }
        #pragma unroll
        for (int s = 0; s < DIM; s++) { Ur[tid][s] = re[s]; Ui[tid][s] = im[s]; }
    }
    __syncthreads();

    // --- Step 2: A_i[p][q] = sum_s z_i(s) Re(conj(U[s,p]) U[s,q]) ---
    {
        const int p = tid >> 4, q = tid & 15;
        float a0 = 0.f, a1 = 0.f, a2 = 0.f, a3 = 0.f;
        #pragma unroll
        for (int s = 0; s < DIM; s++) {
            float rr = Ur[p][s] * Ur[q][s] + Ui[p][s] * Ui[q][s];
            a0 += (s & 8) ? -rr : rr;
            a1 += (s & 4) ? -rr : rr;
            a2 += (s & 2) ? -rr : rr;
            a3 += (s & 1) ? -rr : rr;
        }
        A[0][tid] = a0; A[1][tid] = a1; A[2][tid] = a2; A[3][tid] = a3;
    }
    __syncthreads();

    // --- Step 3: project onto {1,cos,sin}^4 basis ---
    if (tid < NBASIS) {
        int kw[4] = {tid / 27, (tid / 9) % 3, (tid / 3) % 3, tid % 3};
        float acc0 = 0.f, acc1 = 0.f, acc2 = 0.f, acc3 = 0.f;
        #pragma unroll
        for (int m = 0; m < 16; m++) {
            int p = 0, q = 0;
            float wgt = 1.0f / 16.0f;
            #pragma unroll
            for (int w = 0; w < 4; w++) {
                const int opt = (m >> w) & 1;
                const int kk = kw[w];
                int a, bb;
                if (kk == 0)      { a = opt; bb = opt; }
                else if (kk == 1) { a = opt; bb = opt; if (opt) wgt = -wgt; }
                else              { a = opt; bb = 1 - opt; }
                p |= a << (3 - w);
                q |= bb << (3 - w);
            }
            acc0 += wgt * A[0][p * 16 + q];
            acc1 += wgt * A[1][p * 16 + q];
            acc2 += wgt * A[2][p * 16 + q];
            acc3 += wgt * A[3][p * 16 + q];
        }
        g_stage.C[h * NBASIS + tid] = make_float4(acc0, acc1, acc2, acc3);
    }

    // --- Block 0: pack Wt4 / b4 ---
    if (h == 0) {
        for (int i = tid; i < EMBED * 32; i += 256) {
            const int e = i >> 5, j = i & 31;
            ((float*)&g_stage.Wt4[j][0])[e] = W[i];
        }
        if (tid < EMBED) ((float*)g_stage.b4)[tid] = b[tid];
    }
}

// ---------------------------------------------------------------------------
// Main: T=2 tokens/thread sharing every coefficient load (validated R7 shape).
// ---------------------------------------------------------------------------
__global__ __launch_bounds__(128, 4) void qmha_main(
    const float4* __restrict__ x,
    float4*       __restrict__ out,
    int tokens)
{
    __shared__ CoefData sD;
    {
        float4* dst = (float4*)&sD;
        const float4* src = (const float4*)&g_stage;
        for (int i = threadIdx.x; i < COEF_F4; i += 128) dst[i] = src[i];
    }
    __syncthreads();

    const int half = tokens >> 1;
    const int gtid = blockIdx.x * 128 + threadIdx.x;
    if (gtid >= half) return;
    const int t0 = gtid, t1 = gtid + half;

    u64 oA01[8], oA23[8], oB01[8], oB23[8];
    {
        const ulonglong2* bp = (const ulonglong2*)sD.b4;
        #pragma unroll
        for (int e4 = 0; e4 < 8; e4++) {
            const ulonglong2 bv = bp[e4];
            oA01[e4] = bv.x; oA23[e4] = bv.y;
            oB01[e4] = bv.x; oB23[e4] = bv.y;
        }
    }

    #pragma unroll 1
    for (int h = 0; h < NHEADS; h++) {
        const float4 xa = x[t0 * 8 + h];
        const float4 xb = x[t1 * 8 + h];

        float c0a, s0a, c1a, s1a, c2a, s2a, c3a, s3a;
        float c0b, s0b, c1b, s1b, c2b, s2b, c3b, s3b;
        __sincosf(xa.x, &s0a, &c0a); __sincosf(xa.y, &s1a, &c1a);
        __sincosf(xa.z, &s2a, &c2a); __sincosf(xa.w, &s3a, &c3a);
        __sincosf(xb.x, &s0b, &c0b); __sincosf(xb.y, &s1b, &c1b);
        __sincosf(xb.z, &s2b, &c2b); __sincosf(xb.w, &s3b, &c3b);

        // B9 = {1, c3, s3, c2, c2c3, c2s3, s2, s2c3, s2s3}, packed dup
        u64 bdA[9], bdB[9];
        {
            const float B9a[9] = {1.f, c3a, s3a, c2a, c2a * c3a, c2a * s3a,
                                  s2a, s2a * c3a, s2a * s3a};
            const float B9b[9] = {1.f, c3b, s3b, c2b, c2b * c3b, c2b * s3b,
                                  s2b, s2b * c3b, s2b * s3b};
            #pragma unroll
            for (int j = 0; j < 9; j++) {
                bdA[j] = pack2(B9a[j], B9a[j]);
                bdB[j] = pack2(B9b[j], B9b[j]);
            }
        }

        u64 accA01 = 0ull, accA23 = 0ull, accB01 = 0ull, accB23 = 0ull;
        const ulonglong2* Ch = (const ulonglong2*)&sD.C[h * NBASIS];

        // A9[i] = f0[i/3] * f1[i%3], rebuilt per-i (register saver)
        const float f0a[3] = {1.f, c0a, s0a}, f1a[3] = {1.f, c1a, s1a};
        const float f0b[3] = {1.f, c0b, s0b}, f1b[3] = {1.f, c1b, s1b};

        #pragma unroll
        for (int i = 0; i < 9; i++) {
            const float aA = f0a[i / 3] * f1a[i % 3];
            const float aB = f0b[i / 3] * f1b[i % 3];
            const u64 adA = pack2(aA, aA);
            const u64 adB = pack2(aB, aB);

            u64 pA01 = 0ull, pA23 = 0ull, pB01 = 0ull, pB23 = 0ull;
            #pragma unroll
            for (int j = 0; j < 9; j++) {
                const ulonglong2 Cv = Ch[i * 9 + j];   // 1 LDS.128 feeds 4 fma2
                pA01 = fma2(Cv.x, bdA[j], pA01);
                pA23 = fma2(Cv.y, bdA[j], pA23);
                pB01 = fma2(Cv.x, bdB[j], pB01);
                pB23 = fma2(Cv.y, bdB[j], pB23);
            }
            accA01 = fma2(adA, pA01, accA01);
            accA23 = fma2(adA, pA23, accA23);
            accB01 = fma2(adB, pB01, accB01);
            accB23 = fma2(adB, pB23, accB23);
        }

        const float2 evA01 = unpack2(accA01), evA23 = unpack2(accA23);
        const float2 evB01 = unpack2(accB01), evB23 = unpack2(accB23);
        const float evqA[4] = {evA01.x, evA01.y, evA23.x, evA23.y};
        const float evqB[4] = {evB01.x, evB01.y, evB23.x, evB23.y};

        #pragma unroll
        for (int q = 0; q < 4; q++) {
            const u64 edA = pack2(evqA[q], evqA[q]);
            const u64 edB = pack2(evqB[q], evqB[q]);
            const ulonglong2* Wr = (const ulonglong2*)&sD.Wt4[h * 4 + q][0];
            #pragma unroll
            for (int e4 = 0; e4 < 8; e4++) {
                const ulonglong2 wv = Wr[e4];          // 1 LDS.128 feeds 4 fma2
                oA01[e4] = fma2(edA, wv.x, oA01[e4]);
                oA23[e4] = fma2(edA, wv.y, oA23[e4]);
                oB01[e4] = fma2(edB, wv.x, oB01[e4]);
                oB23[e4] = fma2(edB, wv.y, oB23[e4]);
            }
        }
    }

    ulonglong2* opA = (ulonglong2*)(out + t0 * 8);
    ulonglong2* opB = (ulonglong2*)(out + t1 * 8);
    #pragma unroll
    for (int e4 = 0; e4 < 8; e4++) {
        ulonglong2 va; va.x = oA01[e4]; va.y = oA23[e4];
        ulonglong2 vb; vb.x = oB01[e4]; vb.y = oB23[e4];
        opA[e4] = va;
        opB[e4] = vb;
    }
}

extern "C" void kernel_launch(void* const* d_in, const int* in_sizes, int n_in,
                              void* d_out, int out_size) {
    const float* x      = (const float*)d_in[0];
    const float* params = (const float*)d_in[1];
    const float* W      = (const float*)d_in[2];
    const float* b      = (const float*)d_in[3];

    const int tokens = in_sizes[0] / EMBED;   // 131072
    const int half = tokens >> 1;             // 65536 threads

    qmha_precompute<<<NHEADS, 256>>>(params, W, b);

    const int threads = 128;
    const int blocks = (half + threads - 1) / threads;   // 512
    qmha_main<<<blocks, threads>>>((const float4*)x, (float4*)d_out, tokens);
}

// round 9
// speedup vs baseline: 1.3025x; 1.0394x over previous
#include <cuda_runtime.h>

#define NQ      4
#define DIM     16
#define NHEADS  8
#define NLAYERS 2
#define EMBED   32
#define NBASIS  81

typedef unsigned long long u64;

struct CoefData {
    float4 C[NHEADS * NBASIS];   // C[h*81+(i*9+j)]: 4 Z-expval coeffs (q0..q3)
    float4 Wt4[32][8];           // Wt4[jrow][e4].k = W_out[e4*4+k][jrow]
    float4 b4[8];
};
__device__ CoefData g_stage;

#define COEF_F4 ((int)(sizeof(CoefData) / 16))

// ---- packed f32x2 helpers ----
__device__ __forceinline__ u64 fma2(u64 a, u64 b, u64 c) {
    u64 d;
    asm("fma.rn.f32x2 %0, %1, %2, %3;" : "=l"(d) : "l"(a), "l"(b), "l"(c));
    return d;
}
__device__ __forceinline__ u64 pack2(float x, float y) {
    u64 d;
    asm("mov.b64 %0, {%1, %2};" : "=l"(d) : "f"(x), "f"(y));
    return d;
}
__device__ __forceinline__ float2 unpack2(u64 v) {
    float2 r;
    asm("mov.b64 {%0, %1}, %2;" : "=f"(r.x), "=f"(r.y) : "l"(v));
    return r;
}
__device__ __forceinline__ u64 shfl_xor16_u64(u64 v) {
    unsigned lo = (unsigned)v, hi = (unsigned)(v >> 32);
    lo = __shfl_xor_sync(0xffffffffu, lo, 16);
    hi = __shfl_xor_sync(0xffffffffu, hi, 16);
    return ((u64)hi << 32) | (u64)lo;
}

// Fold one head's 4 expvals (packed (q0,q1),(q2,q3)) into one token's outputs.
__device__ __forceinline__ void fold2(u64 ev01, u64 ev23, const float4* Wbase,
                                      u64* o01, u64* o23) {
    const float2 e01 = unpack2(ev01), e23 = unpack2(ev23);
    const float evq[4] = {e01.x, e01.y, e23.x, e23.y};
    #pragma unroll
    for (int q = 0; q < 4; q++) {
        const u64 ed = pack2(evq[q], evq[q]);
        const ulonglong2* Wr = (const ulonglong2*)(Wbase + q * 8);
        #pragma unroll
        for (int e4 = 0; e4 < 8; e4++) {
            const ulonglong2 wv = Wr[e4];
            o01[e4] = fma2(ed, wv.x, o01[e4]);
            o23[e4] = fma2(ed, wv.y, o23[e4]);
        }
    }
}

// ---------------------------------------------------------------------------
// Precompute (R8-validated): grid=8, parallel sincos staging.
// ---------------------------------------------------------------------------
__global__ void qmha_precompute(const float* __restrict__ params,
                                const float* __restrict__ W,
                                const float* __restrict__ b) {
    __shared__ float Ur[DIM][DIM];
    __shared__ float Ui[DIM][DIM];
    __shared__ float A[NQ][DIM * DIM];
    __shared__ float gc[NLAYERS * NQ * 3];
    __shared__ float gs[NLAYERS * NQ * 3];

    const int h   = blockIdx.x;
    const int tid = threadIdx.x;

    if (tid < NLAYERS * NQ * 3) {
        const float th = params[h * NLAYERS * NQ * 3 + tid];
        float s, c;
        __sincosf(0.5f * th, &s, &c);
        gc[tid] = c;
        gs[tid] = s;
    }
    __syncthreads();

    if (tid < DIM) {
        float re[DIM], im[DIM];
        #pragma unroll
        for (int s = 0; s < DIM; s++) { re[s] = 0.f; im[s] = 0.f; }
        re[tid] = 1.f;

        for (int l = 0; l < NLAYERS; l++) {
            for (int w = 0; w < NQ; w++) {
                const int mask = 1 << (3 - w);
                const int gi = (l * NQ + w) * 3;
                const float cx = gc[gi + 0], sx = gs[gi + 0];
                const float cy = gc[gi + 1], sy = gs[gi + 1];
                const float cz = gc[gi + 2], sz = gs[gi + 2];
                #pragma unroll
                for (int s0 = 0; s0 < DIM; s0++) {
                    if (s0 & mask) continue;
                    const int s1 = s0 | mask;
                    float r0 = re[s0], i0 = im[s0], r1 = re[s1], i1 = im[s1];
                    // RX
                    float nr0 = cx * r0 + sx * i1;
                    float ni0 = cx * i0 - sx * r1;
                    float nr1 = sx * i0 + cx * r1;
                    float ni1 = -sx * r0 + cx * i1;
                    // RY
                    r0 = nr0; i0 = ni0; r1 = nr1; i1 = ni1;
                    nr0 = cy * r0 - sy * r1;
                    ni0 = cy * i0 - sy * i1;
                    nr1 = sy * r0 + cy * r1;
                    ni1 = sy * i0 + cy * i1;
                    // RZ
                    r0 = nr0; i0 = ni0; r1 = nr1; i1 = ni1;
                    re[s0] = cz * r0 + sz * i0;
                    im[s0] = cz * i0 - sz * r0;
                    re[s1] = cz * r1 - sz * i1;
                    im[s1] = cz * i1 + sz * r1;
                }
            }
            #pragma unroll
            for (int e = 0; e < NQ; e++) {
                const int c = e, t = (e + 1) & 3;
                const int cm = 1 << (3 - c), tm = 1 << (3 - t);
                #pragma unroll
                for (int s = 0; s < DIM; s++) {
                    if ((s & cm) && !(s & tm)) {
                        const int s2 = s | tm;
                        float tr = re[s]; re[s] = re[s2]; re[s2] = tr;
                        float ti = im[s]; im[s] = im[s2]; im[s2] = ti;
                    }
                }
            }
        }
        #pragma unroll
        for (int s = 0; s < DIM; s++) { Ur[tid][s] = re[s]; Ui[tid][s] = im[s]; }
    }
    __syncthreads();

    {
        const int p = tid >> 4, q = tid & 15;
        float a0 = 0.f, a1 = 0.f, a2 = 0.f, a3 = 0.f;
        #pragma unroll
        for (int s = 0; s < DIM; s++) {
            float rr = Ur[p][s] * Ur[q][s] + Ui[p][s] * Ui[q][s];
            a0 += (s & 8) ? -rr : rr;
            a1 += (s & 4) ? -rr : rr;
            a2 += (s & 2) ? -rr : rr;
            a3 += (s & 1) ? -rr : rr;
        }
        A[0][tid] = a0; A[1][tid] = a1; A[2][tid] = a2; A[3][tid] = a3;
    }
    __syncthreads();

    if (tid < NBASIS) {
        int kw[4] = {tid / 27, (tid / 9) % 3, (tid / 3) % 3, tid % 3};
        float acc0 = 0.f, acc1 = 0.f, acc2 = 0.f, acc3 = 0.f;
        #pragma unroll
        for (int m = 0; m < 16; m++) {
            int p = 0, q = 0;
            float wgt = 1.0f / 16.0f;
            #pragma unroll
            for (int w = 0; w < 4; w++) {
                const int opt = (m >> w) & 1;
                const int kk = kw[w];
                int a, bb;
                if (kk == 0)      { a = opt; bb = opt; }
                else if (kk == 1) { a = opt; bb = opt; if (opt) wgt = -wgt; }
                else              { a = opt; bb = 1 - opt; }
                p |= a << (3 - w);
                q |= bb << (3 - w);
            }
            acc0 += wgt * A[0][p * 16 + q];
            acc1 += wgt * A[1][p * 16 + q];
            acc2 += wgt * A[2][p * 16 + q];
            acc3 += wgt * A[3][p * 16 + q];
        }
        g_stage.C[h * NBASIS + tid] = make_float4(acc0, acc1, acc2, acc3);
    }

    if (h == 0) {
        for (int i = tid; i < EMBED * 32; i += 256) {
            const int e = i >> 5, j = i & 31;
            ((float*)&g_stage.Wt4[j][0])[e] = W[i];
        }
        if (tid < EMBED) ((float*)g_stage.b4)[tid] = b[tid];
    }
}

// ---------------------------------------------------------------------------
// Main: head-split pairing. Lanes (l, l^16) form a pair sharing a token pair
// (t0, t0+half): lane<16 handles heads 0-3, lane>=16 handles heads 4-7, both
// for BOTH tokens (C loads still amortized 2x). After each head, evs are
// exchanged via shfl so each thread accumulates ONE token's 32 outputs.
// 2x warps vs R8 at constant total C-load and FMA work.
// NOTE: grid exactly covers half (65536 = 1024*64) -> no divergent shfl.
// ---------------------------------------------------------------------------
__global__ __launch_bounds__(128, 5) void qmha_main(
    const float4* __restrict__ x,
    float4*       __restrict__ out,
    int tokens)
{
    __shared__ CoefData sD;
    {
        float4* dst = (float4*)&sD;
        const float4* src = (const float4*)&g_stage;
        for (int i = threadIdx.x; i < COEF_F4; i += 128) dst[i] = src[i];
    }
    __syncthreads();

    const int half = tokens >> 1;
    const int lane = threadIdx.x & 31;
    const int hh   = lane >> 4;                               // 0 or 1
    const int pair = blockIdx.x * 64 + (threadIdx.x >> 5) * 16 + (lane & 15);
    const int t0 = pair, t1 = pair + half;
    const int myTok = hh ? t1 : t0;

    // my token's outputs: o01[e4]=(out[4e4],out[4e4+1]), o23=(+2,+3)
    u64 o01[8], o23[8];
    {
        const ulonglong2* bp = (const ulonglong2*)sD.b4;
        #pragma unroll
        for (int e4 = 0; e4 < 8; e4++) {
            const ulonglong2 bv = bp[e4];
            o01[e4] = bv.x; o23[e4] = bv.y;
        }
    }

    #pragma unroll 1
    for (int k = 0; k < 4; k++) {
        const int h = hh * 4 + k;                  // own head
        const float4 xa = x[t0 * 8 + h];
        const float4 xb = x[t1 * 8 + h];

        float c0a, s0a, c1a, s1a, c2a, s2a, c3a, s3a;
        float c0b, s0b, c1b, s1b, c2b, s2b, c3b, s3b;
        __sincosf(xa.x, &s0a, &c0a); __sincosf(xa.y, &s1a, &c1a);
        __sincosf(xa.z, &s2a, &c2a); __sincosf(xa.w, &s3a, &c3a);
        __sincosf(xb.x, &s0b, &c0b); __sincosf(xb.y, &s1b, &c1b);
        __sincosf(xb.z, &s2b, &c2b); __sincosf(xb.w, &s3b, &c3b);

        // B9 tails (j=1..8); B9[0]=1 handled by p-init from Cv.
        u64 bdA[8], bdB[8];
        {
            const float B9a[8] = {c3a, s3a, c2a, c2a * c3a, c2a * s3a,
                                  s2a, s2a * c3a, s2a * s3a};
            const float B9b[8] = {c3b, s3b, c2b, c2b * c3b, c2b * s3b,
                                  s2b, s2b * c3b, s2b * s3b};
            #pragma unroll
            for (int j = 0; j < 8; j++) {
                bdA[j] = pack2(B9a[j], B9a[j]);
                bdB[j] = pack2(B9b[j], B9b[j]);
            }
        }

        const float f0a[3] = {1.f, c0a, s0a}, f1a[3] = {1.f, c1a, s1a};
        const float f0b[3] = {1.f, c0b, s0b}, f1b[3] = {1.f, c1b, s1b};

        u64 accA01, accA23, accB01, accB23;
        const ulonglong2* Ch = (const ulonglong2*)&sD.C[h * NBASIS];

        #pragma unroll
        for (int i = 0; i < 9; i++) {
            const ulonglong2* Ci = Ch + i * 9;
            const ulonglong2 Cv0 = Ci[0];
            u64 pA01 = Cv0.x, pA23 = Cv0.y;    // j=0: B9=1
            u64 pB01 = Cv0.x, pB23 = Cv0.y;
            #pragma unroll
            for (int j = 1; j < 9; j++) {
                const ulonglong2 Cv = Ci[j];
                pA01 = fma2(Cv.x, bdA[j - 1], pA01);
                pA23 = fma2(Cv.y, bdA[j - 1], pA23);
                pB01 = fma2(Cv.x, bdB[j - 1], pB01);
                pB23 = fma2(Cv.y, bdB[j - 1], pB23);
            }
            if (i == 0) {                       // A9[0]=1
                accA01 = pA01; accA23 = pA23;
                accB01 = pB01; accB23 = pB23;
            } else {
                const float aA = f0a[i / 3] * f1a[i % 3];
                const float aB = f0b[i / 3] * f1b[i % 3];
                const u64 adA = pack2(aA, aA);
                const u64 adB = pack2(aB, aB);
                accA01 = fma2(adA, pA01, accA01);
                accA23 = fma2(adA, pA23, accA23);
                accB01 = fma2(adB, pB01, accB01);
                accB23 = fma2(adB, pB23, accB23);
            }
        }

        // Exchange: I keep my token's evs for my head; I send the OTHER
        // token's evs and receive my token's evs for the partner head (h^4).
        const u64 s0 = hh ? accA01 : accB01;
        const u64 s1 = hh ? accA23 : accB23;
        const u64 r0 = shfl_xor16_u64(s0);
        const u64 r1 = shfl_xor16_u64(s1);
        const u64 m0 = hh ? accB01 : accA01;
        const u64 m1 = hh ? accB23 : accA23;

        fold2(m0, m1, &sD.Wt4[h * 4][0], o01, o23);          // own head
        fold2(r0, r1, &sD.Wt4[(h ^ 4) * 4][0], o01, o23);    // partner head
    }

    ulonglong2* op = (ulonglong2*)(out + myTok * 8);
    #pragma unroll
    for (int e4 = 0; e4 < 8; e4++) {
        ulonglong2 v;
        v.x = o01[e4];
        v.y = o23[e4];
        op[e4] = v;
    }
}

extern "C" void kernel_launch(void* const* d_in, const int* in_sizes, int n_in,
                              void* d_out, int out_size) {
    const float* x      = (const float*)d_in[0];
    const float* params = (const float*)d_in[1];
    const float* W      = (const float*)d_in[2];
    const float* b      = (const float*)d_in[3];

    const int tokens = in_sizes[0] / EMBED;   // 131072
    const int half = tokens >> 1;             // 65536 pairs

    qmha_precompute<<<NHEADS, 256>>>(params, W, b);

    const int threads = 128;                  // 64 pairs per block
    const int blocks = (half + 63) / 64;      // 1024
    qmha_main<<<blocks, threads>>>((const float4*)x, (float4*)d_out, tokens);
}